// round 1
// baseline (speedup 1.0000x reference)
#include <cuda_runtime.h>
#include <cstdint>

#define IN_F   4096
#define OUT_F  4096
#define B_DIM  4096

// Dense scatter target for the COO weight. 64 MB static device array
// (allocation-free scratch per harness rules).
__device__ float g_W[(size_t)OUT_F * IN_F];

// ---------------------------------------------------------------------------
// Kernel 1: zero the dense weight buffer (must run every launch: graph replay
// repeats the scatter, and duplicates accumulate).
// ---------------------------------------------------------------------------
__global__ void zero_w_kernel() {
    size_t n4 = (size_t)OUT_F * IN_F / 4;
    float4* p = reinterpret_cast<float4*>(g_W);
    size_t stride = (size_t)gridDim.x * blockDim.x;
    for (size_t i = (size_t)blockIdx.x * blockDim.x + threadIdx.x; i < n4; i += stride)
        p[i] = make_float4(0.f, 0.f, 0.f, 0.f);
}

// ---------------------------------------------------------------------------
// Kernel 2: scatter COO triplets into dense W. atomicAdd handles duplicate
// (row,col) pairs with COO accumulate semantics.
// ---------------------------------------------------------------------------
__global__ void scatter_kernel(const float* __restrict__ vals,
                               const int* __restrict__ rows,
                               const int* __restrict__ cols,
                               int nnz) {
    int i = blockIdx.x * blockDim.x + threadIdx.x;
    if (i < nnz) {
        atomicAdd(&g_W[(size_t)rows[i] * IN_F + cols[i]], vals[i]);
    }
}

// ---------------------------------------------------------------------------
// Kernel 3: C = x @ W^T + bias   (both operands K-major: NT GEMM)
// 128x128 CTA tile, BK=16, 256 threads, 8x8 micro-tile per thread.
// Inner product uses packed fma.rn.f32x2 (SASS FFMA2): 2 FMA per instruction,
// doubling fp32 throughput vs scalar FFMA on sm_103a.
// ---------------------------------------------------------------------------
#define BM 128
#define BN 128
#define BK 16
#define SPAD 4
#define SSTR (BM + SPAD)   // 132 floats; 132 % 4 == 0 keeps float4/u64x2 alignment

__device__ __forceinline__ unsigned long long fma2(unsigned long long a,
                                                   unsigned long long b,
                                                   unsigned long long c) {
    unsigned long long d;
    asm("fma.rn.f32x2 %0, %1, %2, %3;" : "=l"(d) : "l"(a), "l"(b), "l"(c));
    return d;
}

__device__ __forceinline__ unsigned long long pack_dup(float v) {
    unsigned long long d;
    asm("mov.b64 %0, {%1, %2};" : "=l"(d) : "f"(v), "f"(v));
    return d;
}

__device__ __forceinline__ void unpack2(unsigned long long p, float& lo, float& hi) {
    asm("mov.b64 {%0, %1}, %2;" : "=f"(lo), "=f"(hi) : "l"(p));
}

__global__ __launch_bounds__(256, 2)
void gemm_nt_kernel(const float* __restrict__ x,
                    const float* __restrict__ bias,
                    float* __restrict__ out) {
    __shared__ float As[BK][SSTR];
    __shared__ float Bs[BK][SSTR];

    const int tid = threadIdx.x;
    const int tx  = tid & 15;        // 0..15 -> n direction
    const int ty  = tid >> 4;        // 0..15 -> m direction
    const int m0  = blockIdx.y * BM;
    const int n0  = blockIdx.x * BN;

    // 8x8 accumulator as 8x4 packed f32x2 pairs (pairs along n)
    unsigned long long acc[8][4];
#pragma unroll
    for (int i = 0; i < 8; i++)
#pragma unroll
        for (int j = 0; j < 4; j++) acc[i][j] = 0ull;

    const float* xA = x   + (size_t)m0 * IN_F;
    const float* wB = g_W + (size_t)n0 * IN_F;

    for (int k0 = 0; k0 < IN_F; k0 += BK) {
        // Stage A and B tiles (transposed to [k][m]) — 512 float4 each,
        // 2 per thread.
#pragma unroll
        for (int s = 0; s < 2; s++) {
            int f4 = tid + s * 256;          // 0..511
            int r  = f4 >> 2;                // tile row 0..127
            int c4 = f4 & 3;                 // which float4 along k
            float4 va = *reinterpret_cast<const float4*>(
                xA + (size_t)r * IN_F + k0 + c4 * 4);
            As[c4 * 4 + 0][r] = va.x;
            As[c4 * 4 + 1][r] = va.y;
            As[c4 * 4 + 2][r] = va.z;
            As[c4 * 4 + 3][r] = va.w;
            float4 vb = *reinterpret_cast<const float4*>(
                wB + (size_t)r * IN_F + k0 + c4 * 4);
            Bs[c4 * 4 + 0][r] = vb.x;
            Bs[c4 * 4 + 1][r] = vb.y;
            Bs[c4 * 4 + 2][r] = vb.z;
            Bs[c4 * 4 + 3][r] = vb.w;
        }
        __syncthreads();

#pragma unroll
        for (int kk = 0; kk < BK; kk++) {
            // A fragment: 8 floats (broadcast across 16 lanes sharing ty)
            float4 a0 = *reinterpret_cast<const float4*>(&As[kk][ty * 8]);
            float4 a1 = *reinterpret_cast<const float4*>(&As[kk][ty * 8 + 4]);
            float av[8] = {a0.x, a0.y, a0.z, a0.w, a1.x, a1.y, a1.z, a1.w};

            // B fragment: 8 floats as 4 packed pairs (16B loads, aligned)
            const ulonglong2* bp =
                reinterpret_cast<const ulonglong2*>(&Bs[kk][tx * 8]);
            ulonglong2 b01 = bp[0];
            ulonglong2 b23 = bp[1];
            unsigned long long bd[4] = {b01.x, b01.y, b23.x, b23.y};

#pragma unroll
            for (int i = 0; i < 8; i++) {
                unsigned long long ad = pack_dup(av[i]);
#pragma unroll
                for (int j = 0; j < 4; j++)
                    acc[i][j] = fma2(ad, bd[j], acc[i][j]);
            }
        }
        __syncthreads();
    }

    // Epilogue: unpack, add bias, store
    const int nbase = n0 + tx * 8;
    float bv[8];
#pragma unroll
    for (int j = 0; j < 8; j++) bv[j] = bias[nbase + j];

#pragma unroll
    for (int i = 0; i < 8; i++) {
        float* cp = out + (size_t)(m0 + ty * 8 + i) * OUT_F + nbase;
#pragma unroll
        for (int j = 0; j < 4; j++) {
            float lo, hi;
            unpack2(acc[i][j], lo, hi);
            float2 v = make_float2(lo + bv[2 * j], hi + bv[2 * j + 1]);
            *reinterpret_cast<float2*>(cp + 2 * j) = v;
        }
    }
}

// ---------------------------------------------------------------------------
// kernel_launch: zero -> scatter -> GEMM, all graph-capturable.
// Input order (metadata): x, values, rows, cols, bias
// ---------------------------------------------------------------------------
extern "C" void kernel_launch(void* const* d_in, const int* in_sizes, int n_in,
                              void* d_out, int out_size) {
    const float* x    = (const float*)d_in[0];
    const float* vals = (const float*)d_in[1];
    const int*   rows = (const int*)d_in[2];
    const int*   cols = (const int*)d_in[3];
    const float* bias = (const float*)d_in[4];
    float*       out  = (float*)d_out;
    const int nnz = in_sizes[1];

    zero_w_kernel<<<2048, 256>>>();
    scatter_kernel<<<(nnz + 255) / 256, 256>>>(vals, rows, cols, nnz);
    dim3 grid(OUT_F / BN, B_DIM / BM);
    gemm_nt_kernel<<<grid, 256>>>(x, bias, out);
}

// round 3
// speedup vs baseline: 3.4856x; 3.4856x over previous
#include <cuda_runtime.h>
#include <cstdint>

#define IN_F   4096
#define OUT_F  4096
#define B_DIM  4096

// 64 MB dense weight scratch + 64 MB tf32-rounded activation scratch.
__device__ float g_W[(size_t)OUT_F * IN_F];
__device__ float g_X[(size_t)B_DIM * IN_F];

// ---------------------------------------------------------------------------
// Kernel 1: zero dense W (graph replays re-run the scatter, so re-zero)
// ---------------------------------------------------------------------------
__global__ void zero_w_kernel() {
    size_t n4 = (size_t)OUT_F * IN_F / 4;
    float4* p = reinterpret_cast<float4*>(g_W);
    size_t stride = (size_t)gridDim.x * blockDim.x;
    for (size_t i = (size_t)blockIdx.x * blockDim.x + threadIdx.x; i < n4; i += stride)
        p[i] = make_float4(0.f, 0.f, 0.f, 0.f);
}

// ---------------------------------------------------------------------------
// Kernel 2: COO scatter with atomicAdd (duplicates accumulate)
// ---------------------------------------------------------------------------
__global__ void scatter_kernel(const float* __restrict__ vals,
                               const int* __restrict__ rows,
                               const int* __restrict__ cols, int nnz) {
    int i = blockIdx.x * blockDim.x + threadIdx.x;
    if (i < nnz)
        atomicAdd(&g_W[(size_t)rows[i] * IN_F + cols[i]], vals[i]);
}

// ---------------------------------------------------------------------------
// Kernel 3: round W (in place) and x (into g_X) to tf32 round-to-nearest.
// mma.sync truncates inputs to tf32; pre-rounding keeps the error unbiased.
// ---------------------------------------------------------------------------
__device__ __forceinline__ float rna_tf32(float v) {
    uint32_t r;
    asm("cvt.rna.tf32.f32 %0, %1;" : "=r"(r) : "f"(v));
    return __uint_as_float(r);
}

__global__ void round_kernel(const float* __restrict__ x) {
    size_t n4 = (size_t)OUT_F * IN_F / 4;
    float4* w4 = reinterpret_cast<float4*>(g_W);
    float4* xo = reinterpret_cast<float4*>(g_X);
    const float4* xi = reinterpret_cast<const float4*>(x);
    size_t stride = (size_t)gridDim.x * blockDim.x;
    for (size_t i = (size_t)blockIdx.x * blockDim.x + threadIdx.x; i < n4; i += stride) {
        float4 w = w4[i];
        w.x = rna_tf32(w.x); w.y = rna_tf32(w.y);
        w.z = rna_tf32(w.z); w.w = rna_tf32(w.w);
        w4[i] = w;
        float4 v = xi[i];
        v.x = rna_tf32(v.x); v.y = rna_tf32(v.y);
        v.z = rna_tf32(v.z); v.w = rna_tf32(v.w);
        xo[i] = v;
    }
}

// ---------------------------------------------------------------------------
// Kernel 4: tf32 mma.sync GEMM   out = g_X @ g_W^T + bias
// CTA 128x128, BK=32, 8 warps (2x4 -> warp tile 64x32), 3-stage cp.async.
// SMEM tiles padded to 36-float rows: conflict-free fragment loads and
// 16B-aligned cp.async destinations (144B row stride).
// ---------------------------------------------------------------------------
#define BM 128
#define BN 128
#define BK 32
#define KITERS (IN_F / BK)          // 128
#define NSTAGE 3
#define SA 36                       // floats per SMEM row (pad 4)
#define TILE_F (128 * SA)           // floats per tile (A or B): 4608
#define STAGE_F (2 * TILE_F)        // floats per stage: 9216
#define SMEM_BYTES (NSTAGE * STAGE_F * 4)   // 110592

__device__ __forceinline__ void cp_async16(uint32_t saddr, const void* gptr) {
    asm volatile("cp.async.cg.shared.global [%0], [%1], 16;"
                 :: "r"(saddr), "l"(gptr) : "memory");
}

__device__ __forceinline__ uint32_t smem_u32(const void* p) {
    uint32_t a;
    asm("{ .reg .u64 t; cvta.to.shared.u64 t, %1; cvt.u32.u64 %0, t; }"
        : "=r"(a) : "l"(p));
    return a;
}

__device__ __forceinline__ void mma_tf32(float* c, const uint32_t* a,
                                         const uint32_t* b) {
    asm volatile(
        "mma.sync.aligned.m16n8k8.row.col.f32.tf32.tf32.f32 "
        "{%0,%1,%2,%3}, {%4,%5,%6,%7}, {%8,%9}, {%0,%1,%2,%3};"
        : "+f"(c[0]), "+f"(c[1]), "+f"(c[2]), "+f"(c[3])
        : "r"(a[0]), "r"(a[1]), "r"(a[2]), "r"(a[3]), "r"(b[0]), "r"(b[1]));
}

__global__ __launch_bounds__(256)
void gemm_mma_kernel(const float* __restrict__ bias, float* __restrict__ out) {
    extern __shared__ float smem[];
    const uint32_t sb = smem_u32(smem);

    const int tid  = threadIdx.x;
    const int wid  = tid >> 5;
    const int lane = tid & 31;
    const int wm   = wid & 1;        // 0..1  -> 64 M-rows each
    const int wn   = wid >> 1;       // 0..3  -> 32 N-cols each
    const int g    = lane >> 2;      // group 0..7
    const int tig  = lane & 3;       // thread-in-group

    const int m0 = blockIdx.y * BM;
    const int n0 = blockIdx.x * BN;

    const float* Ag = g_X + (size_t)m0 * IN_F;
    const float* Bg = g_W + (size_t)n0 * IN_F;

    // per-thread cp.async chunk coords: 1024 16B-chunks per tile, 4 per thread
    const int crow0 = tid >> 3;          // rows tid>>3, +32, +64, +96
    const int cc8   = tid & 7;           // 16B slot within 128B row

    float acc[4][4][4];                  // [mtile][ntile][reg]
#pragma unroll
    for (int i = 0; i < 4; i++)
#pragma unroll
        for (int j = 0; j < 4; j++)
#pragma unroll
            for (int r = 0; r < 4; r++) acc[i][j][r] = 0.f;

    // ---- prologue: prefetch stages 0 and 1 ----
#pragma unroll
    for (int st = 0; st < 2; st++) {
        const int k0 = st * BK;
        const uint32_t ab = sb + st * (STAGE_F * 4);
        const uint32_t bb = ab + TILE_F * 4;
#pragma unroll
        for (int j = 0; j < 4; j++) {
            int row = crow0 + j * 32;
            uint32_t so = (uint32_t)(row * (SA * 4) + cc8 * 16);
            cp_async16(ab + so, Ag + (size_t)row * IN_F + k0 + cc8 * 4);
            cp_async16(bb + so, Bg + (size_t)row * IN_F + k0 + cc8 * 4);
        }
        asm volatile("cp.async.commit_group;" ::: "memory");
    }

    // ---- mainloop ----
    for (int ci = 0; ci < KITERS; ci++) {
        asm volatile("cp.async.wait_group 1;" ::: "memory");
        __syncthreads();

        // prefetch stage ci+2 (overwrites stage (ci-1)%3; reads done last iter)
        if (ci + 2 < KITERS) {
            const int st = (ci + 2) % NSTAGE;
            const int k0 = (ci + 2) * BK;
            const uint32_t ab = sb + st * (STAGE_F * 4);
            const uint32_t bb = ab + TILE_F * 4;
#pragma unroll
            for (int j = 0; j < 4; j++) {
                int row = crow0 + j * 32;
                uint32_t so = (uint32_t)(row * (SA * 4) + cc8 * 16);
                cp_async16(ab + so, Ag + (size_t)row * IN_F + k0 + cc8 * 4);
                cp_async16(bb + so, Bg + (size_t)row * IN_F + k0 + cc8 * 4);
            }
        }
        asm volatile("cp.async.commit_group;" ::: "memory");

        // compute on stage ci%3
        const float* As = smem + (ci % NSTAGE) * STAGE_F;
        const float* Bs = As + TILE_F;
#pragma unroll
        for (int kk = 0; kk < 4; kk++) {
            const int k = kk * 8 + tig;
            uint32_t af[4][4];
#pragma unroll
            for (int i = 0; i < 4; i++) {
                const int m = wm * 64 + i * 16 + g;
                af[i][0] = __float_as_uint(As[m * SA + k]);
                af[i][1] = __float_as_uint(As[(m + 8) * SA + k]);
                af[i][2] = __float_as_uint(As[m * SA + k + 4]);
                af[i][3] = __float_as_uint(As[(m + 8) * SA + k + 4]);
            }
            uint32_t bf[4][2];
#pragma unroll
            for (int j = 0; j < 4; j++) {
                const int n = wn * 32 + j * 8 + g;
                bf[j][0] = __float_as_uint(Bs[n * SA + k]);
                bf[j][1] = __float_as_uint(Bs[n * SA + k + 4]);
            }
#pragma unroll
            for (int i = 0; i < 4; i++)
#pragma unroll
                for (int j = 0; j < 4; j++)
                    mma_tf32(acc[i][j], af[i], bf[j]);
        }
    }

    // ---- epilogue: bias + store ----
#pragma unroll
    for (int i = 0; i < 4; i++) {
        const int row = m0 + wm * 64 + i * 16 + g;
#pragma unroll
        for (int j = 0; j < 4; j++) {
            const int col = n0 + wn * 32 + j * 8 + tig * 2;
            float2 bv = *reinterpret_cast<const float2*>(bias + col);
            float2 v0 = make_float2(acc[i][j][0] + bv.x, acc[i][j][1] + bv.y);
            float2 v1 = make_float2(acc[i][j][2] + bv.x, acc[i][j][3] + bv.y);
            *reinterpret_cast<float2*>(out + (size_t)row * OUT_F + col) = v0;
            *reinterpret_cast<float2*>(out + (size_t)(row + 8) * OUT_F + col) = v1;
        }
    }
}

// ---------------------------------------------------------------------------
// kernel_launch: zero -> scatter -> round -> mma GEMM (all graph-capturable)
// Inputs: x, values, rows, cols, bias
// ---------------------------------------------------------------------------
extern "C" void kernel_launch(void* const* d_in, const int* in_sizes, int n_in,
                              void* d_out, int out_size) {
    const float* x    = (const float*)d_in[0];
    const float* vals = (const float*)d_in[1];
    const int*   rows = (const int*)d_in[2];
    const int*   cols = (const int*)d_in[3];
    const float* bias = (const float*)d_in[4];
    float*       out  = (float*)d_out;
    const int nnz = in_sizes[1];

    cudaFuncSetAttribute(gemm_mma_kernel,
                         cudaFuncAttributeMaxDynamicSharedMemorySize, SMEM_BYTES);

    zero_w_kernel<<<2048, 256>>>();
    scatter_kernel<<<(nnz + 255) / 256, 256>>>(vals, rows, cols, nnz);
    round_kernel<<<2048, 256>>>(x);
    dim3 grid(OUT_F / BN, B_DIM / BM);
    gemm_mma_kernel<<<grid, 256, SMEM_BYTES>>>(bias, out);
}